// round 2
// baseline (speedup 1.0000x reference)
#include <cuda_runtime.h>

// out = relu( GroupNorm32( Wv @ feat + bv, gn_v_g, gn_v_b ) )
// The softmax-weighted sum in the reference collapses to identity because
// v is constant along the softmax axis (rows of softmax sum to 1).
//
// Shapes: feat [B=2, C=128, N=512], Wv [128,128], out [2,128,512].
// One block per (batch, group): 64 blocks, 256 threads.
// Group = 4 consecutive channels x 512 points = 2048 values.
// Each thread: 2 points x 4 channels, all in registers.

#define C_CH   128
#define NPT    512
#define CH_PER_G 4
#define EPS_GN 1e-5f
#define NTHREADS 256

__global__ __launch_bounds__(NTHREADS, 4)
void fused_v_gn_relu_kernel(const float* __restrict__ feat,
                            const float* __restrict__ Wv,
                            const float* __restrict__ bv,
                            const float* __restrict__ gamma,
                            const float* __restrict__ beta,
                            float* __restrict__ out) {
    const int g  = blockIdx.x & 31;   // group 0..31
    const int b  = blockIdx.x >> 5;   // batch 0..1
    const int c0 = g * CH_PER_G;      // first channel of group
    const int t  = threadIdx.x;       // 0..255

    __shared__ float wv_s[CH_PER_G * C_CH];   // 4 rows of Wv
    __shared__ float red_s[2 * (NTHREADS / 32)];
    __shared__ float stat_s[2];               // mean, inv_std

    // Stage the 4 Wv rows for this group's channels into smem.
    #pragma unroll
    for (int i = t; i < CH_PER_G * C_CH; i += NTHREADS)
        wv_s[i] = Wv[c0 * C_CH + i];
    __syncthreads();

    const float* fb = feat + (size_t)b * C_CH * NPT;
    const int n0 = t;          // point 0 for this thread
    const int n1 = t + 256;    // point 1

    float acc[2][CH_PER_G];
    #pragma unroll
    for (int c = 0; c < CH_PER_G; c++) {
        const float bvc = bv[c0 + c];
        acc[0][c] = bvc;
        acc[1][c] = bvc;
    }

    // v[c0+c, n] = sum_cc Wv[c0+c, cc] * feat[b, cc, n] + bv[c0+c]
    #pragma unroll 4
    for (int cc = 0; cc < C_CH; cc++) {
        const float f0 = fb[cc * NPT + n0];
        const float f1 = fb[cc * NPT + n1];
        #pragma unroll
        for (int c = 0; c < CH_PER_G; c++) {
            const float w = wv_s[c * C_CH + cc];
            acc[0][c] = fmaf(w, f0, acc[0][c]);
            acc[1][c] = fmaf(w, f1, acc[1][c]);
        }
    }

    // Local sum / sumsq over this thread's 8 values.
    float s = 0.f, ss = 0.f;
    #pragma unroll
    for (int p = 0; p < 2; p++)
        #pragma unroll
        for (int c = 0; c < CH_PER_G; c++) {
            const float v = acc[p][c];
            s  += v;
            ss = fmaf(v, v, ss);
        }

    // Warp reduce.
    #pragma unroll
    for (int off = 16; off > 0; off >>= 1) {
        s  += __shfl_xor_sync(0xffffffffu, s,  off);
        ss += __shfl_xor_sync(0xffffffffu, ss, off);
    }
    const int lane = t & 31, wid = t >> 5;
    if (lane == 0) {
        red_s[wid] = s;
        red_s[(NTHREADS / 32) + wid] = ss;
    }
    __syncthreads();
    if (t == 0) {
        float ts = 0.f, tss = 0.f;
        #pragma unroll
        for (int w = 0; w < NTHREADS / 32; w++) {
            ts  += red_s[w];
            tss += red_s[(NTHREADS / 32) + w];
        }
        const float inv_n = 1.0f / (CH_PER_G * NPT);
        const float m  = ts * inv_n;
        const float var = tss * inv_n - m * m;   // biased, matches jnp.var
        stat_s[0] = m;
        stat_s[1] = rsqrtf(var + EPS_GN);
    }
    __syncthreads();

    const float m   = stat_s[0];
    const float rst = stat_s[1];

    float* ob = out + (size_t)b * C_CH * NPT;
    #pragma unroll
    for (int c = 0; c < CH_PER_G; c++) {
        const float ga = gamma[c0 + c] * rst;
        const float be = beta[c0 + c];
        const float y0 = fmaf(acc[0][c] - m, ga, be);
        const float y1 = fmaf(acc[1][c] - m, ga, be);
        ob[(c0 + c) * NPT + n0] = fmaxf(y0, 0.f);
        ob[(c0 + c) * NPT + n1] = fmaxf(y1, 0.f);
    }
}

extern "C" void kernel_launch(void* const* d_in, const int* in_sizes, int n_in,
                              void* d_out, int out_size) {
    // metadata order:
    // 0 feat, 1 Wk, 2 bk, 3 Wq, 4 bq, 5 Wv, 6 bv, 7 gn_v_g, 8 gn_v_b,
    // 9 gn1_g, 10 gn1_b, 11 W1, 12 b1, 13 gn2_g, 14 gn2_b, 15 W2, 16 b2
    const float* feat  = (const float*)d_in[0];
    const float* Wv    = (const float*)d_in[5];
    const float* bv    = (const float*)d_in[6];
    const float* gn_g  = (const float*)d_in[7];
    const float* gn_b  = (const float*)d_in[8];
    float* out = (float*)d_out;

    (void)in_sizes; (void)n_in; (void)out_size;

    fused_v_gn_relu_kernel<<<64, NTHREADS>>>(feat, Wv, bv, gn_g, gn_b, out);
}

// round 3
// speedup vs baseline: 1.0201x; 1.0201x over previous
#include <cuda_runtime.h>

// out = relu( GroupNorm32( Wv @ feat + bv, gn_v_g, gn_v_b ) )
// (softmax-weighted sum in the reference is identity: v is constant along the
//  softmax axis and softmax rows sum to 1).
//
// Shapes: feat [B=2, C=128, N=512], Wv [128,128], out [2,128,512].
// Grid: 128 blocks = B(2) x group(32) x slice(2).  256 threads/block.
// Each block: 256 points x 4 group channels; thread = 1 point x 4 channels.
// Cross-slice GN stats via device-global partials + parity-flag handshake
// (each replay adds exactly 2 arrivals per group -> spin until flag is even;
//  no reset needed across CUDA-graph replays; 128 blocks <= 148 SMs so both
//  partners are always co-resident -> no deadlock).

#define C_CH     128
#define NPT      512
#define CH_PER_G 4
#define EPS_GN   1e-5f
#define NTHREADS 256
#define SLICES   2
#define PTS_PER_SLICE (NPT / SLICES)

__device__ float    g_part[2][32][SLICES][2];  // [b][g][slice][{sum, sumsq}]
__device__ unsigned g_flag[2][32];             // zero-init at module load

__global__ __launch_bounds__(NTHREADS)
void fused_v_gn_relu_kernel(const float* __restrict__ feat,
                            const float* __restrict__ Wv,
                            const float* __restrict__ bv,
                            const float* __restrict__ gamma,
                            const float* __restrict__ beta,
                            float* __restrict__ out) {
    const int x  = blockIdx.x;
    const int s  = x & 1;            // slice 0..1
    const int g  = (x >> 1) & 31;    // group 0..31
    const int b  = x >> 6;           // batch 0..1
    const int c0 = g * CH_PER_G;
    const int t  = threadIdx.x;
    const int n  = s * PTS_PER_SLICE + t;   // this thread's point

    __shared__ float wv_s[CH_PER_G * C_CH];
    __shared__ float red_s[2 * (NTHREADS / 32)];
    __shared__ float stat_s[2];

    // Stage 4 rows of Wv (broadcast reads later).
    #pragma unroll
    for (int i = t; i < CH_PER_G * C_CH; i += NTHREADS)
        wv_s[i] = Wv[c0 * C_CH + i];
    __syncthreads();

    const float* fb = feat + (size_t)b * C_CH * NPT;

    float acc[CH_PER_G];
    #pragma unroll
    for (int c = 0; c < CH_PER_G; c++) acc[c] = bv[c0 + c];

    // v[c0+c, n] = sum_cc Wv[c0+c, cc] * feat[b, cc, n] + bv[c0+c]
    #pragma unroll 8
    for (int cc = 0; cc < C_CH; cc++) {
        const float f = fb[cc * NPT + n];
        acc[0] = fmaf(wv_s[0 * C_CH + cc], f, acc[0]);
        acc[1] = fmaf(wv_s[1 * C_CH + cc], f, acc[1]);
        acc[2] = fmaf(wv_s[2 * C_CH + cc], f, acc[2]);
        acc[3] = fmaf(wv_s[3 * C_CH + cc], f, acc[3]);
    }

    // Local partial sum / sumsq over this thread's 4 values.
    float ps = 0.f, pss = 0.f;
    #pragma unroll
    for (int c = 0; c < CH_PER_G; c++) {
        ps  += acc[c];
        pss  = fmaf(acc[c], acc[c], pss);
    }
    #pragma unroll
    for (int off = 16; off > 0; off >>= 1) {
        ps  += __shfl_xor_sync(0xffffffffu, ps,  off);
        pss += __shfl_xor_sync(0xffffffffu, pss, off);
    }
    const int lane = t & 31, wid = t >> 5;
    if (lane == 0) {
        red_s[wid] = ps;
        red_s[(NTHREADS / 32) + wid] = pss;
    }
    __syncthreads();

    if (t == 0) {
        float ts = 0.f, tss = 0.f;
        #pragma unroll
        for (int w = 0; w < NTHREADS / 32; w++) {
            ts  += red_s[w];
            tss += red_s[(NTHREADS / 32) + w];
        }
        // Publish this slice's partial, then arrive.
        g_part[b][g][s][0] = ts;
        g_part[b][g][s][1] = tss;
        __threadfence();
        atomicAdd(&g_flag[b][g], 1u);

        // Wait for both slices of this replay: flag becomes even.
        volatile unsigned* fp = &g_flag[b][g];
        while ((*fp) & 1u) { }
        __threadfence();

        // Deterministic combine order: slice 0 then slice 1.
        const float tot_s  = g_part[b][g][0][0] + g_part[b][g][1][0];
        const float tot_ss = g_part[b][g][0][1] + g_part[b][g][1][1];
        const float inv_n  = 1.0f / (float)(CH_PER_G * NPT);
        const float m      = tot_s * inv_n;
        const float var    = tot_ss * inv_n - m * m;   // biased (jnp.var)
        stat_s[0] = m;
        stat_s[1] = rsqrtf(var + EPS_GN);
    }
    __syncthreads();

    const float m   = stat_s[0];
    const float rst = stat_s[1];

    float* ob = out + (size_t)b * C_CH * NPT;
    #pragma unroll
    for (int c = 0; c < CH_PER_G; c++) {
        const float ga = gamma[c0 + c] * rst;
        const float be = beta[c0 + c];
        const float y  = fmaf(acc[c] - m, ga, be);
        ob[(c0 + c) * NPT + n] = fmaxf(y, 0.f);
    }
}

extern "C" void kernel_launch(void* const* d_in, const int* in_sizes, int n_in,
                              void* d_out, int out_size) {
    // metadata order:
    // 0 feat, 1 Wk, 2 bk, 3 Wq, 4 bq, 5 Wv, 6 bv, 7 gn_v_g, 8 gn_v_b,
    // 9 gn1_g, 10 gn1_b, 11 W1, 12 b1, 13 gn2_g, 14 gn2_b, 15 W2, 16 b2
    const float* feat = (const float*)d_in[0];
    const float* Wv   = (const float*)d_in[5];
    const float* bv   = (const float*)d_in[6];
    const float* gn_g = (const float*)d_in[7];
    const float* gn_b = (const float*)d_in[8];
    float* out = (float*)d_out;

    (void)in_sizes; (void)n_in; (void)out_size;

    fused_v_gn_relu_kernel<<<2 * 32 * SLICES, NTHREADS>>>(feat, Wv, bv,
                                                          gn_g, gn_b, out);
}

// round 4
// speedup vs baseline: 1.4536x; 1.4250x over previous
#include <cuda_runtime.h>

// out = relu( GroupNorm32( Wv @ feat + bv, gn_v_g, gn_v_b ) )
// (softmax-weighted sum in the reference is identity: v is constant along the
//  softmax axis and softmax rows sum to 1).
//
// feat [2,128,512], Wv [128,128], out [2,128,512].
// Grid: 128 blocks = B(2) x group(32) x slice(2), 128 threads.
// Thread = 2 consecutive points (float2) x 4 group channels.
// Main loop: double-buffered chunks of 16 cc -> L2 latency hidden by
// 128 FMA-insts (~256 cyc) per chunk.  Weights transposed in smem so one
// broadcast LDS.128 yields all 4 channel weights per cc.
// Cross-slice GN stats via device-global partials + parity-flag handshake
// (each replay adds exactly 2 arrivals/group; spin until even; blocks <= SMs
//  so both partners co-resident -> no deadlock; graph-replay safe, no reset).

#define C_CH     128
#define NPT      512
#define CH_PER_G 4
#define EPS_GN   1e-5f
#define NTHREADS 128
#define SLICES   2
#define CHUNK    16

__device__ float    g_part[2][32][SLICES][2];  // [b][g][slice][{sum,sumsq}]
__device__ unsigned g_flag[2][32];             // zero-init at module load

__global__ __launch_bounds__(NTHREADS, 1)
void fused_v_gn_relu_kernel(const float* __restrict__ feat,
                            const float* __restrict__ Wv,
                            const float* __restrict__ bv,
                            const float* __restrict__ gamma,
                            const float* __restrict__ beta,
                            float* __restrict__ out) {
    const int x  = blockIdx.x;
    const int s  = x & 1;            // slice 0..1
    const int g  = (x >> 1) & 31;    // group 0..31
    const int b  = x >> 6;           // batch 0..1
    const int c0 = g * CH_PER_G;
    const int t  = threadIdx.x;      // 0..127

    __shared__ float  wt_s[C_CH * CH_PER_G];   // transposed: [cc][c], 2KB
    __shared__ float  red_s[2 * (NTHREADS / 32)];
    __shared__ float  stat_s[2];

    // Stage Wv transposed: wt_s[cc*4 + c] = Wv[(c0+c)*128 + cc].
    // Thread i handles cc = i, all 4 c.
    {
        const int cc = t;
        #pragma unroll
        for (int c = 0; c < CH_PER_G; c++)
            wt_s[cc * CH_PER_G + c] = Wv[(c0 + c) * C_CH + cc];
    }
    __syncthreads();

    // float2 view of feat row-space: row cc has 256 float2; this thread's
    // column within the row is s*128 + t.
    const float2* fp = (const float2*)(feat + (size_t)b * C_CH * NPT)
                       + s * (NPT / 2 / SLICES) + t;
    const float4* wt4 = (const float4*)wt_s;

    float2 acc[CH_PER_G];
    #pragma unroll
    for (int c = 0; c < CH_PER_G; c++) {
        const float bvc = bv[c0 + c];
        acc[c].x = bvc; acc[c].y = bvc;
    }

    // Software-pipelined mainloop, chunks of CHUNK cc.
    float2 cur[CHUNK], nxt[CHUNK];
    #pragma unroll
    for (int i = 0; i < CHUNK; i++) cur[i] = fp[i * (NPT / 2)];

    #pragma unroll
    for (int cb = 0; cb < C_CH; cb += CHUNK) {
        if (cb + CHUNK < C_CH) {
            #pragma unroll
            for (int i = 0; i < CHUNK; i++)
                nxt[i] = fp[(cb + CHUNK + i) * (NPT / 2)];
        }
        #pragma unroll
        for (int i = 0; i < CHUNK; i++) {
            const float4 w = wt4[cb + i];          // broadcast LDS.128
            const float2 f = cur[i];
            acc[0].x = fmaf(w.x, f.x, acc[0].x);
            acc[0].y = fmaf(w.x, f.y, acc[0].y);
            acc[1].x = fmaf(w.y, f.x, acc[1].x);
            acc[1].y = fmaf(w.y, f.y, acc[1].y);
            acc[2].x = fmaf(w.z, f.x, acc[2].x);
            acc[2].y = fmaf(w.z, f.y, acc[2].y);
            acc[3].x = fmaf(w.w, f.x, acc[3].x);
            acc[3].y = fmaf(w.w, f.y, acc[3].y);
        }
        #pragma unroll
        for (int i = 0; i < CHUNK; i++) cur[i] = nxt[i];
    }

    // Local partial sum / sumsq over this thread's 8 values.
    float ps = 0.f, pss = 0.f;
    #pragma unroll
    for (int c = 0; c < CH_PER_G; c++) {
        ps  += acc[c].x + acc[c].y;
        pss  = fmaf(acc[c].x, acc[c].x, pss);
        pss  = fmaf(acc[c].y, acc[c].y, pss);
    }
    #pragma unroll
    for (int off = 16; off > 0; off >>= 1) {
        ps  += __shfl_xor_sync(0xffffffffu, ps,  off);
        pss += __shfl_xor_sync(0xffffffffu, pss, off);
    }
    const int lane = t & 31, wid = t >> 5;
    if (lane == 0) {
        red_s[wid] = ps;
        red_s[(NTHREADS / 32) + wid] = pss;
    }
    __syncthreads();

    if (t == 0) {
        float ts = 0.f, tss = 0.f;
        #pragma unroll
        for (int w = 0; w < NTHREADS / 32; w++) {
            ts  += red_s[w];
            tss += red_s[(NTHREADS / 32) + w];
        }
        g_part[b][g][s][0] = ts;
        g_part[b][g][s][1] = tss;
        __threadfence();
        atomicAdd(&g_flag[b][g], 1u);

        volatile unsigned* fl = &g_flag[b][g];
        while ((*fl) & 1u) { }
        __threadfence();

        const float tot_s  = g_part[b][g][0][0] + g_part[b][g][1][0];
        const float tot_ss = g_part[b][g][0][1] + g_part[b][g][1][1];
        const float inv_n  = 1.0f / (float)(CH_PER_G * NPT);
        const float m      = tot_s * inv_n;
        const float var    = tot_ss * inv_n - m * m;   // biased (jnp.var)
        stat_s[0] = m;
        stat_s[1] = rsqrtf(var + EPS_GN);
    }
    __syncthreads();

    const float m   = stat_s[0];
    const float rst = stat_s[1];

    float2* ob = (float2*)(out + (size_t)b * C_CH * NPT);
    const int col = s * (NPT / 2 / SLICES) + t;
    #pragma unroll
    for (int c = 0; c < CH_PER_G; c++) {
        const float ga = gamma[c0 + c] * rst;
        const float be = beta[c0 + c];
        float2 y;
        y.x = fmaxf(fmaf(acc[c].x - m, ga, be), 0.f);
        y.y = fmaxf(fmaf(acc[c].y - m, ga, be), 0.f);
        ob[(c0 + c) * (NPT / 2) + col] = y;
    }
}

extern "C" void kernel_launch(void* const* d_in, const int* in_sizes, int n_in,
                              void* d_out, int out_size) {
    // metadata order:
    // 0 feat, 1 Wk, 2 bk, 3 Wq, 4 bq, 5 Wv, 6 bv, 7 gn_v_g, 8 gn_v_b,
    // 9 gn1_g, 10 gn1_b, 11 W1, 12 b1, 13 gn2_g, 14 gn2_b, 15 W2, 16 b2
    const float* feat = (const float*)d_in[0];
    const float* Wv   = (const float*)d_in[5];
    const float* bv   = (const float*)d_in[6];
    const float* gn_g = (const float*)d_in[7];
    const float* gn_b = (const float*)d_in[8];
    float* out = (float*)d_out;

    (void)in_sizes; (void)n_in; (void)out_size;

    fused_v_gn_relu_kernel<<<2 * 32 * SLICES, NTHREADS>>>(feat, Wv, bv,
                                                          gn_g, gn_b, out);
}